// round 15
// baseline (speedup 1.0000x reference)
#include <cuda_runtime.h>
#include <cuda_fp16.h>
#include <cstdint>
#include <cstddef>

#define T_SEQ 1024
typedef unsigned long long u64t;

// ---------------------------------------------------------------------------
// All dynamic exchange via tagged u64 words:
//   [15:0] f16 v_even | [31:16] f16 v_odd | [39:32] e5m2 lo_even |
//   [47:40] e5m2 lo_odd | [63:48] tag (= step+1)
// h:   g_hT [L3][parity2][bg4][2048]
// seq: g_sAT/g_sBT [t*4+bg][2048]  (layer0/layer1 outputs)
// x0:  untagged u32 frag pairs (precomputed, no sync needed)
// ---------------------------------------------------------------------------
__device__ u64t     g_hT[3 * 2 * 4 * 2048];
__device__ u64t     g_sAT[(size_t)4096 * 2048];     // 64 MB
__device__ u64t     g_sBT[(size_t)4096 * 2048];     // 64 MB
__device__ uint32_t g_x0_hi[(size_t)4096 * 1024];
__device__ uint32_t g_x0_lo[(size_t)4096 * 1024];
__device__ uint32_t g_mbits[64 * 32];
__device__ int      g_maxlen[4];                    // per-bg max row length

// ---------------------------------------------------------------------------
// Init (every replay): clear ALL tags (h + seq), build mask bits + maxlen.
// grid 8192 x 256 = 2,097,152 threads; each clears 4 u64 per seq array.
// ---------------------------------------------------------------------------
__global__ void init_kernel(const float* __restrict__ x)
{
    int gi = (int)(blockIdx.x * blockDim.x + threadIdx.x);
    if (gi < 3 * 2 * 4 * 2048) g_hT[gi] = 0ull;
    {
        size_t base = (size_t)gi * 4;
        uint4 z = make_uint4(0u, 0u, 0u, 0u);
        *reinterpret_cast<uint4*>(g_sAT + base)     = z;
        *reinterpret_cast<uint4*>(g_sAT + base + 2) = z;
        *reinterpret_cast<uint4*>(g_sBT + base)     = z;
        *reinterpret_cast<uint4*>(g_sBT + base + 2) = z;
    }
    int warp = gi >> 5;
    int lane = threadIdx.x & 31;
    if (warp < 64 * T_SEQ) {
        const float4* p = reinterpret_cast<const float4*>(x) + (size_t)warp * 32;
        float4 v = p[lane];
        bool nz = (v.x != 0.0f) || (v.y != 0.0f) || (v.z != 0.0f) || (v.w != 0.0f);
        unsigned bl = __ballot_sync(0xffffffffu, nz);
        if (lane == 0 && bl) {
            int row = warp >> 10, t = warp & 1023;
            atomicOr(&g_mbits[row * 32 + (t >> 5)], 1u << (t & 31));
            atomicMax(&g_maxlen[row >> 4], t + 1);
        }
    }
}

// ---------------------------------------------------------------------------
static __device__ __forceinline__ void split2(float a, float b, uint32_t& hi, uint32_t& lo)
{
    __half h0 = __float2half_rn(a), h1 = __float2half_rn(b);
    __half l0 = __float2half_rn(a - __half2float(h0));
    __half l1 = __float2half_rn(b - __half2float(h1));
    __half2 H = __halves2half2(h0, h1), L = __halves2half2(l0, l1);
    hi = *reinterpret_cast<uint32_t*>(&H);
    lo = *reinterpret_cast<uint32_t*>(&L);
}
static __device__ __forceinline__ void mma16816(float* d, uint32_t a0, uint32_t a1,
                                                uint32_t a2, uint32_t a3,
                                                uint32_t b0, uint32_t b1)
{
    asm volatile("mma.sync.aligned.m16n8k16.row.col.f32.f16.f16.f32 "
                 "{%0,%1,%2,%3}, {%4,%5,%6,%7}, {%8,%9}, {%0,%1,%2,%3};"
                 : "+f"(d[0]), "+f"(d[1]), "+f"(d[2]), "+f"(d[3])
                 : "r"(a0), "r"(a1), "r"(a2), "r"(a3), "r"(b0), "r"(b1));
}
static __device__ __forceinline__ u64t ld_rlx64(const u64t* p)
{
    u64t v;
    asm volatile("ld.relaxed.gpu.global.u64 %0, [%1];" : "=l"(v) : "l"(p) : "memory");
    return v;
}
static __device__ __forceinline__ void st_rlx64(u64t* p, u64t v)
{
    asm volatile("st.relaxed.gpu.global.u64 [%0], %1;" :: "l"(p), "l"(v) : "memory");
}
static __device__ __forceinline__ uint4 ld_cg_u4(const uint32_t* p)
{
    uint4 v;
    asm volatile("ld.global.cg.v4.u32 {%0,%1,%2,%3}, [%4];"
                 : "=r"(v.x), "=r"(v.y), "=r"(v.z), "=r"(v.w) : "l"(p));
    return v;
}
static __device__ __forceinline__ float sigx(float x)
{
    return __fdividef(1.0f, 1.0f + __expf(-x));
}
static __device__ __forceinline__ float tanhx(float x)
{
    return __fdividef(2.0f, 1.0f + __expf(-2.0f * x)) - 1.0f;
}

// ---------------------------------------------------------------------------
__global__ void convert_x(const float* __restrict__ x)
{
    int wid  = (int)(blockIdx.x * 8 + (threadIdx.x >> 5));
    int lane = threadIdx.x & 31;
    if (wid >= 32768) return;
    int t = wid >> 5, rem = wid & 31, bg = rem >> 3, s = rem & 7;
    int nl = lane >> 2, q = lane & 3;
    const float* p0 = x + ((size_t)(bg * 16 + nl) * T_SEQ + t) * 128;
    const float* p1 = x + ((size_t)(bg * 16 + nl + 8) * T_SEQ + t) * 128;
    int k0 = s * 16 + 2 * q, k1 = k0 + 8;
    float2 v00 = *reinterpret_cast<const float2*>(p0 + k0);
    float2 v01 = *reinterpret_cast<const float2*>(p0 + k1);
    float2 v10 = *reinterpret_cast<const float2*>(p1 + k0);
    float2 v11 = *reinterpret_cast<const float2*>(p1 + k1);
    uint32_t a0h, a0l, a1h, a1l, a2h, a2l, a3h, a3l;
    split2(v00.x, v00.y, a0h, a0l);
    split2(v10.x, v10.y, a1h, a1l);
    split2(v01.x, v01.y, a2h, a2l);
    split2(v11.x, v11.y, a3h, a3l);
    size_t o = (size_t)(t * 4 + bg) * 1024 + s * 128 + lane * 4;
    *reinterpret_cast<uint4*>(&g_x0_hi[o]) = make_uint4(a0h, a1h, a2h, a3h);
    *reinterpret_cast<uint4*>(&g_x0_lo[o]) = make_uint4(a0l, a1l, a2l, a3l);
}

// ---------------------------------------------------------------------------
// Per-quad layer engine. h AND x (layers 1/2) via tagged u64 channels;
// one named barrier per step; loop bounded by ragged tmax.
// ---------------------------------------------------------------------------
template <int XS4, bool TAGX>
static __device__ __forceinline__ void run_layer(
    int L, int bg, int ug, int lane, int sub, int tq, int tmax,
    const uint32_t* w_frag, int woff, float* pb0, float* pb1,
    const uint32_t* msk_sh,
    const uint32_t* x_hi, const uint32_t* x_lo,   // TAGX=false (layer0)
    const u64t* xT,                               // TAGX=true  (layers 1/2)
    u64t* soT,                                    // seq out (L0/L1) or null
    const float* __restrict__ bias)
{
    const int q = lane & 3, nl = lane >> 2;
    const int gr = tq >> 3, gu = tq & 7;
    const int unit = ug * 8 + gu;
    float bias4[4];
    #pragma unroll
    for (int g = 0; g < 4; g++) bias4[g] = bias[g * 256 + unit];

    const int ds = unit >> 4, dp = (unit >> 1) & 7, dhalf = unit & 1;
    const int dnl = gr & 7;
    const int dj = (dp >= 4 ? 2 : 0) + (gr >= 8 ? 1 : 0);
    const int du = ds * 128 + (dnl * 4 + (dp & 3)) * 4 + dj;
    const size_t hA0 = ((size_t)(L * 2 + 0) * 4 + bg) * 2048;
    const size_t hA1 = ((size_t)(L * 2 + 1) * 4 + bg) * 2048;

    float c_reg = 0.0f, h_reg = 0.0f;
    const int barA = L + 1;

    for (int t = 0; t < tmax; t++) {
        float D[4][4];
        #pragma unroll
        for (int i = 0; i < 4; i++)
            #pragma unroll
            for (int j = 0; j < 4; j++) D[i][j] = 0.0f;

        // ---- x part ----
        if (TAGX) {
            const u64t* xb = xT + (size_t)(t * 4 + bg) * 2048;
            #pragma unroll
            for (int si = 0; si < XS4; si++) {
                const u64t* xp = xb + (sub * XS4 + si) * 128 + lane * 4;
                u64t v0, v1, v2, v3;
                unsigned tg = (unsigned)(t + 1);
                for (;;) {
                    v0 = ld_rlx64(xp);     v1 = ld_rlx64(xp + 1);
                    v2 = ld_rlx64(xp + 2); v3 = ld_rlx64(xp + 3);
                    bool ok = ((unsigned)(v0 >> 48) == tg) &
                              ((unsigned)(v1 >> 48) == tg) &
                              ((unsigned)(v2 >> 48) == tg) &
                              ((unsigned)(v3 >> 48) == tg);
                    if (__all_sync(0xffffffffu, ok)) break;
                }
                uint32_t Ah0 = (uint32_t)v0, Ah1 = (uint32_t)v1;
                uint32_t Ah2 = (uint32_t)v2, Ah3 = (uint32_t)v3;
                uint32_t Al0 = __byte_perm((uint32_t)(v0 >> 32), 0, 0x1404);
                uint32_t Al1 = __byte_perm((uint32_t)(v1 >> 32), 0, 0x1404);
                uint32_t Al2 = __byte_perm((uint32_t)(v2 >> 32), 0, 0x1404);
                uint32_t Al3 = __byte_perm((uint32_t)(v3 >> 32), 0, 0x1404);
                #pragma unroll
                for (int i = 0; i < 4; i++) {
                    uint4 B = *reinterpret_cast<const uint4*>(
                        &w_frag[woff + (si * 4 + i) * 128 + lane * 4]);
                    mma16816(D[i], Ah0, Ah1, Ah2, Ah3, B.x, B.y);
                    mma16816(D[i], Al0, Al1, Al2, Al3, B.x, B.y);
                    mma16816(D[i], Ah0, Ah1, Ah2, Ah3, B.z, B.w);
                }
            }
        } else {
            #pragma unroll
            for (int si = 0; si < XS4; si++) {
                const uint32_t* xh = x_hi + (size_t)(t * 4 + bg) * 1024
                                     + (sub * XS4 + si) * 128 + lane * 4;
                const uint32_t* xl = x_lo + (size_t)(t * 4 + bg) * 1024
                                     + (sub * XS4 + si) * 128 + lane * 4;
                uint4 Ah = ld_cg_u4(xh);
                uint4 Al = ld_cg_u4(xl);
                #pragma unroll
                for (int i = 0; i < 4; i++) {
                    uint4 B = *reinterpret_cast<const uint4*>(
                        &w_frag[woff + (si * 4 + i) * 128 + lane * 4]);
                    mma16816(D[i], Ah.x, Ah.y, Ah.z, Ah.w, B.x, B.y);
                    mma16816(D[i], Al.x, Al.y, Al.z, Al.w, B.x, B.y);
                    mma16816(D[i], Ah.x, Ah.y, Ah.z, Ah.w, B.z, B.w);
                }
            }
        }

        // ---- h part (tagged channel) ----
        if (t > 0) {
            const u64t* hb = g_hT + ((t & 1) ? hA1 : hA0);
            #pragma unroll
            for (int si = 0; si < 4; si++) {
                const u64t* hp = hb + (sub * 4 + si) * 128 + lane * 4;
                u64t v0, v1, v2, v3;
                unsigned tg = (unsigned)t;
                for (;;) {
                    v0 = ld_rlx64(hp);     v1 = ld_rlx64(hp + 1);
                    v2 = ld_rlx64(hp + 2); v3 = ld_rlx64(hp + 3);
                    bool ok = ((unsigned)(v0 >> 48) == tg) &
                              ((unsigned)(v1 >> 48) == tg) &
                              ((unsigned)(v2 >> 48) == tg) &
                              ((unsigned)(v3 >> 48) == tg);
                    if (__all_sync(0xffffffffu, ok)) break;
                }
                uint32_t Ah0 = (uint32_t)v0, Ah1 = (uint32_t)v1;
                uint32_t Ah2 = (uint32_t)v2, Ah3 = (uint32_t)v3;
                uint32_t Al0 = __byte_perm((uint32_t)(v0 >> 32), 0, 0x1404);
                uint32_t Al1 = __byte_perm((uint32_t)(v1 >> 32), 0, 0x1404);
                uint32_t Al2 = __byte_perm((uint32_t)(v2 >> 32), 0, 0x1404);
                uint32_t Al3 = __byte_perm((uint32_t)(v3 >> 32), 0, 0x1404);
                #pragma unroll
                for (int i = 0; i < 4; i++) {
                    uint4 B = *reinterpret_cast<const uint4*>(
                        &w_frag[woff + ((XS4 + si) * 4 + i) * 128 + lane * 4]);
                    mma16816(D[i], Ah0, Ah1, Ah2, Ah3, B.x, B.y);
                    mma16816(D[i], Al0, Al1, Al2, Al3, B.x, B.y);
                    mma16816(D[i], Ah0, Ah1, Ah2, Ah3, B.z, B.w);
                }
            }
        }

        // ---- quad split-K partials + single barrier ----
        float* pb = (t & 1) ? pb1 : pb0;
        #pragma unroll
        for (int i = 0; i < 4; i++) {
            *reinterpret_cast<float2*>(&pb[nl * 130 + sub * 32 + i * 8 + 2 * q]) =
                make_float2(D[i][0], D[i][1]);
            *reinterpret_cast<float2*>(&pb[(nl + 8) * 130 + sub * 32 + i * 8 + 2 * q]) =
                make_float2(D[i][2], D[i][3]);
        }
        asm volatile("bar.sync %0, 128;" :: "r"(barA) : "memory");

        // ---- gates ----
        float z[4];
        #pragma unroll
        for (int g = 0; g < 4; g++) {
            float a = bias4[g];
            #pragma unroll
            for (int w4 = 0; w4 < 4; w4++)
                a += pb[gr * 130 + w4 * 32 + g * 8 + gu];
            z[g] = a;
        }
        float si_ = sigx(z[0]), sf_ = sigx(z[1]), so_ = sigx(z[3]);
        float cn = sf_ * c_reg + si_ * tanhx(z[2]);
        float hn = so_ * tanhx(cn);
        bool m = (msk_sh[gr * 32 + (t >> 5)] >> (t & 31)) & 1u;
        if (!m) { cn = c_reg; hn = h_reg; }
        c_reg = cn; h_reg = hn;

        // ---- pack with partner lane, publish tagged u64 (h + seq) ----
        uint32_t vh = (uint32_t)__half_as_ushort(__float2half_rn(hn));
        float rres = hn - __half2float(__ushort_as_half((unsigned short)vh));
        uint32_t vl = (uint32_t)__half_as_ushort(__float2half_rn(rres));
        uint32_t hv = vh | (vl << 16);
        uint32_t pv = __shfl_xor_sync(0xffffffffu, hv, 1);
        if (dhalf == 0) {
            uint32_t hi_pair = (hv & 0xffffu) | (pv << 16);
            uint32_t lbA = ((hv >> 16) + 0x80u) >> 8 & 0xffu;
            uint32_t lbB = ((pv >> 16) + 0x80u) >> 8 & 0xffu;
            u64t val = (u64t)hi_pair | ((u64t)(lbA | (lbB << 8)) << 32)
                     | ((u64t)(unsigned)(t + 1) << 48);
            st_rlx64(g_hT + ((t & 1) ? hA0 : hA1) + du, val);   // parity (t+1)&1
            if (soT) st_rlx64(soT + (size_t)(t * 4 + bg) * 2048 + du, val);
        }
    }
}

// ---------------------------------------------------------------------------
// 128 blocks (bg4 x ug32) x 384 threads = 3 layer-quads of 4 warps.
// ---------------------------------------------------------------------------
__global__ void __launch_bounds__(384, 1)
lstm_fused(const float* __restrict__ W0, const float* __restrict__ U0, const float* __restrict__ b0,
           const float* __restrict__ W1, const float* __restrict__ U1, const float* __restrict__ b1,
           const float* __restrict__ W2, const float* __restrict__ U2, const float* __restrict__ b2)
{
    extern __shared__ uint32_t smw[];
    uint32_t* w_frag = smw;                                       // 45056 u32
    float*    p_sh   = reinterpret_cast<float*>(smw + 45056);     // 6 x 2080
    uint32_t* msk_sh = reinterpret_cast<uint32_t*>(p_sh + 12480); // 512

    const int tid  = threadIdx.x;
    const int lane = tid & 31;
    const int warp = tid >> 5;
    const int L    = warp >> 2;
    const int sub  = warp & 3;
    const int tq   = tid & 127;
    const int bg   = blockIdx.x & 3;
    const int ug   = blockIdx.x >> 2;
    const int q    = lane & 3, nl = lane >> 2;

    for (int i = tid; i < 512; i += 384)
        msk_sh[i] = g_mbits[(bg * 16 + (i >> 5)) * 32 + (i & 31)];

    const float* W = (L == 0) ? W0 : (L == 1) ? W1 : W2;
    const float* U = (L == 0) ? U0 : (L == 1) ? U1 : U2;
    const float* bias = (L == 0) ? b0 : (L == 1) ? b1 : b2;
    const int KIN  = (L == 0) ? 128 : 256;
    const int XS4r = (L == 0) ? 2 : 4;
    const int woff = (L == 0) ? sub * 3072 : 12288 + (L - 1) * 16384 + sub * 4096;

    for (int slot = 0; slot < XS4r + 4; slot++) {
        int kg = (slot < XS4r) ? (sub * XS4r + slot) * 16
                               : KIN + (sub * 4 + slot - XS4r) * 16;
        #pragma unroll
        for (int i = 0; i < 4; i++) {
            int gcol = i * 256 + ug * 8 + nl;
            auto wu = [&](int k) -> float {
                return (k < KIN) ? W[(size_t)k * 1024 + gcol]
                                 : U[(size_t)(k - KIN) * 1024 + gcol];
            };
            int k0 = kg + 2 * q;
            uint32_t b0h, b0l, b1h, b1l;
            split2(wu(k0),     wu(k0 + 1), b0h, b0l);
            split2(wu(k0 + 8), wu(k0 + 9), b1h, b1l);
            *reinterpret_cast<uint4*>(&w_frag[woff + (slot * 4 + i) * 128 + lane * 4]) =
                make_uint4(b0h, b1h, b0l, b1l);
        }
    }
    __syncthreads();

    const int tmax = g_maxlen[bg];
    float* pb0 = p_sh + (L * 2 + 0) * 2080;
    float* pb1 = p_sh + (L * 2 + 1) * 2080;

    if (L == 0)
        run_layer<2, false>(0, bg, ug, lane, sub, tq, tmax, w_frag, woff, pb0, pb1,
                            msk_sh, g_x0_hi, g_x0_lo, nullptr, g_sAT, b0);
    else if (L == 1)
        run_layer<4, true>(1, bg, ug, lane, sub, tq, tmax, w_frag, woff, pb0, pb1,
                           msk_sh, nullptr, nullptr, g_sAT, g_sBT, b1);
    else
        run_layer<4, true>(2, bg, ug, lane, sub, tq, tmax, w_frag, woff, pb0, pb1,
                           msk_sh, nullptr, nullptr, g_sBT, nullptr, b2);
}

// ---------------------------------------------------------------------------
__global__ void final_kernel(const float* __restrict__ dw,
                             const float* __restrict__ db,
                             float* __restrict__ out)
{
    int p = blockIdx.x, lane = threadIdx.x;
    int rA = 2 * p;
    int parity = g_maxlen[rA >> 4] & 1;            // last publish slot
    float s_acc = 0.0f;
    for (int pi = lane; pi < 128; pi += 32) {      // unit-pair index
        int unit = 2 * pi;
        int ds = unit >> 4, dp = pi & 7;
        float a0, a1, b0, b1;
        #pragma unroll
        for (int k = 0; k < 2; k++) {
            int r = rA + k;
            int bgr = r >> 4, rl = r & 15, nl2 = rl & 7;
            int dj = (dp >= 4 ? 2 : 0) + (rl >= 8 ? 1 : 0);
            size_t idx = ((size_t)(2 * 2 + parity) * 4 + bgr) * 2048
                       + ds * 128 + (nl2 * 4 + (dp & 3)) * 4 + dj;
            u64t v = g_hT[idx];
            float e0 = __half2float(__ushort_as_half((unsigned short)(v & 0xffffu)))
                     + __half2float(__ushort_as_half((unsigned short)(((v >> 32) & 0xffu) << 8)));
            float e1 = __half2float(__ushort_as_half((unsigned short)((v >> 16) & 0xffffu)))
                     + __half2float(__ushort_as_half((unsigned short)(((v >> 40) & 0xffu) << 8)));
            if (k == 0) { a0 = e0; a1 = e1; } else { b0 = e0; b1 = e1; }
        }
        float d0 = a0 - b0, d1 = a1 - b1;
        s_acc += d0 * d0 + d1 * d1;
    }
    #pragma unroll
    for (int off = 16; off; off >>= 1) s_acc += __shfl_xor_sync(0xffffffffu, s_acc, off);
    if (lane == 0) {
        float dist = sqrtf(s_acc);
        dist = fminf(fmaxf(dist, 1e-7f), 1e7f);
        out[p] = 1.0f / (1.0f + expf(-(dist * dw[0] + db[0])));
    }
}

// ---------------------------------------------------------------------------
extern "C" void kernel_launch(void* const* d_in, const int* in_sizes, int n_in,
                              void* d_out, int out_size)
{
    (void)in_sizes; (void)n_in; (void)out_size;
    const float* x  = (const float*)d_in[0];
    const float* W0 = (const float*)d_in[1];
    const float* U0 = (const float*)d_in[2];
    const float* b0 = (const float*)d_in[3];
    const float* W1 = (const float*)d_in[4];
    const float* U1 = (const float*)d_in[5];
    const float* b1 = (const float*)d_in[6];
    const float* W2 = (const float*)d_in[7];
    const float* U2 = (const float*)d_in[8];
    const float* b2 = (const float*)d_in[9];
    const float* dw = (const float*)d_in[10];
    const float* db = (const float*)d_in[11];
    float* out = (float*)d_out;

    const size_t smem = 45056u * 4 + 12480u * 4 + 512u * 4;   // 232192 B
    cudaFuncSetAttribute(lstm_fused, cudaFuncAttributeMaxDynamicSharedMemorySize,
                         (int)smem);

    init_kernel<<<8192, 256>>>(x);
    convert_x<<<4096, 256>>>(x);
    lstm_fused<<<128, 384, smem>>>(W0, U0, b0, W1, U1, b1, W2, U2, b2);
    final_kernel<<<32, 32>>>(dw, db, out);
}

// round 17
// speedup vs baseline: 1.1749x; 1.1749x over previous
#include <cuda_runtime.h>
#include <cuda_fp16.h>
#include <cstdint>
#include <cstddef>

#define T_SEQ 1024
typedef unsigned long long u64t;

// ---------------------------------------------------------------------------
// h exchange: tagged u64 per k-pair, [L3][parity2][bg4][2048]:
//   [15:0] f16 h_even | [31:16] f16 h_odd | [39:32] e5m2 lo_even |
//   [47:40] e5m2 lo_odd | [63:48] tag = step+1
// x/seq: untagged u32 frag pairs (hi/lo f16 k-pairs) + per-quad flags.
// ---------------------------------------------------------------------------
__device__ u64t     g_hT[3 * 2 * 4 * 2048];
__device__ uint32_t g_x0_hi[(size_t)4096 * 1024];
__device__ uint32_t g_x0_lo[(size_t)4096 * 1024];
__device__ uint32_t g_sA_hi[(size_t)4096 * 2048];
__device__ uint32_t g_sA_lo[(size_t)4096 * 2048];
__device__ uint32_t g_sB_hi[(size_t)4096 * 2048];
__device__ uint32_t g_sB_lo[(size_t)4096 * 2048];
__device__ uint32_t g_mbits[64 * 32];
__device__ unsigned g_qflag[2 * 4 * 32];            // [layer<2][bg][ug]
__device__ int      g_maxlen[4];                    // per-bg max row length

// ---------------------------------------------------------------------------
__global__ void init_kernel(const float* __restrict__ x)
{
    if (blockIdx.x == 0)
        for (int i = threadIdx.x; i < 2 * 4 * 32; i += blockDim.x) g_qflag[i] = 0u;
    int gi = (int)(blockIdx.x * blockDim.x + threadIdx.x);
    if (gi < 3 * 2 * 4 * 2048) g_hT[gi] = 0ull;     // clear h tags every replay
    int warp = gi >> 5;
    int lane = threadIdx.x & 31;
    if (warp < 64 * T_SEQ) {
        const float4* p = reinterpret_cast<const float4*>(x) + (size_t)warp * 32;
        float4 v = p[lane];
        bool nz = (v.x != 0.0f) || (v.y != 0.0f) || (v.z != 0.0f) || (v.w != 0.0f);
        unsigned bl = __ballot_sync(0xffffffffu, nz);
        if (lane == 0 && bl) {
            int row = warp >> 10, t = warp & 1023;
            atomicOr(&g_mbits[row * 32 + (t >> 5)], 1u << (t & 31));
            atomicMax(&g_maxlen[row >> 4], t + 1);  // idempotent across replays
        }
    }
}

// ---------------------------------------------------------------------------
static __device__ __forceinline__ void split2(float a, float b, uint32_t& hi, uint32_t& lo)
{
    __half h0 = __float2half_rn(a), h1 = __float2half_rn(b);
    __half l0 = __float2half_rn(a - __half2float(h0));
    __half l1 = __float2half_rn(b - __half2float(h1));
    __half2 H = __halves2half2(h0, h1), L = __halves2half2(l0, l1);
    hi = *reinterpret_cast<uint32_t*>(&H);
    lo = *reinterpret_cast<uint32_t*>(&L);
}
static __device__ __forceinline__ void mma16816(float* d, uint32_t a0, uint32_t a1,
                                                uint32_t a2, uint32_t a3,
                                                uint32_t b0, uint32_t b1)
{
    asm volatile("mma.sync.aligned.m16n8k16.row.col.f32.f16.f16.f32 "
                 "{%0,%1,%2,%3}, {%4,%5,%6,%7}, {%8,%9}, {%0,%1,%2,%3};"
                 : "+f"(d[0]), "+f"(d[1]), "+f"(d[2]), "+f"(d[3])
                 : "r"(a0), "r"(a1), "r"(a2), "r"(a3), "r"(b0), "r"(b1));
}
static __device__ __forceinline__ unsigned ld_acq(const unsigned* p)
{
    unsigned v;
    asm volatile("ld.acquire.gpu.global.u32 %0, [%1];" : "=r"(v) : "l"(p) : "memory");
    return v;
}
static __device__ __forceinline__ void st_rel(unsigned* p, unsigned v)
{
    asm volatile("st.release.gpu.global.u32 [%0], %1;" :: "l"(p), "r"(v) : "memory");
}
static __device__ __forceinline__ u64t ld_rlx64(const u64t* p)
{
    u64t v;
    asm volatile("ld.relaxed.gpu.global.u64 %0, [%1];" : "=l"(v) : "l"(p) : "memory");
    return v;
}
static __device__ __forceinline__ void st_rlx64(u64t* p, u64t v)
{
    asm volatile("st.relaxed.gpu.global.u64 [%0], %1;" :: "l"(p), "l"(v) : "memory");
}
static __device__ __forceinline__ void st_cg_u32(uint32_t* p, uint32_t v)
{
    asm volatile("st.global.cg.u32 [%0], %1;" :: "l"(p), "r"(v) : "memory");
}
static __device__ __forceinline__ uint4 ld_cg_u4(const uint32_t* p)
{
    uint4 v;
    asm volatile("ld.global.cg.v4.u32 {%0,%1,%2,%3}, [%4];"
                 : "=r"(v.x), "=r"(v.y), "=r"(v.z), "=r"(v.w) : "l"(p));
    return v;
}
static __device__ __forceinline__ float sigx(float x)
{
    return __fdividef(1.0f, 1.0f + __expf(-x));
}
static __device__ __forceinline__ float tanhx(float x)
{
    return __fdividef(2.0f, 1.0f + __expf(-2.0f * x)) - 1.0f;
}

// ---------------------------------------------------------------------------
__global__ void convert_x(const float* __restrict__ x)
{
    int wid  = (int)(blockIdx.x * 8 + (threadIdx.x >> 5));
    int lane = threadIdx.x & 31;
    if (wid >= 32768) return;
    int t = wid >> 5, rem = wid & 31, bg = rem >> 3, s = rem & 7;
    int nl = lane >> 2, q = lane & 3;
    const float* p0 = x + ((size_t)(bg * 16 + nl) * T_SEQ + t) * 128;
    const float* p1 = x + ((size_t)(bg * 16 + nl + 8) * T_SEQ + t) * 128;
    int k0 = s * 16 + 2 * q, k1 = k0 + 8;
    float2 v00 = *reinterpret_cast<const float2*>(p0 + k0);
    float2 v01 = *reinterpret_cast<const float2*>(p0 + k1);
    float2 v10 = *reinterpret_cast<const float2*>(p1 + k0);
    float2 v11 = *reinterpret_cast<const float2*>(p1 + k1);
    uint32_t a0h, a0l, a1h, a1l, a2h, a2l, a3h, a3l;
    split2(v00.x, v00.y, a0h, a0l);
    split2(v10.x, v10.y, a1h, a1l);
    split2(v01.x, v01.y, a2h, a2l);
    split2(v11.x, v11.y, a3h, a3l);
    size_t o = (size_t)(t * 4 + bg) * 1024 + s * 128 + lane * 4;
    *reinterpret_cast<uint4*>(&g_x0_hi[o]) = make_uint4(a0h, a1h, a2h, a3h);
    *reinterpret_cast<uint4*>(&g_x0_lo[o]) = make_uint4(a0l, a1l, a2l, a3l);
}

// ---------------------------------------------------------------------------
// Per-quad layer engine: 4 warps, K/4 per warp.  h via tagged u64 channel;
// x via flags (layers 1/2).  Loop bounded by ragged tmax (all-masked tail
// is skip-safe: h/c frozen, downstream never reads beyond tmax).
// ---------------------------------------------------------------------------
template <int XS4, int XD>
static __device__ __forceinline__ void run_layer(
    int L, int bg, int ug, int lane, int sub, int tq, int tmax,
    const uint32_t* w_frag, int woff, float* pb0, float* pb1,
    const uint32_t* msk_sh,
    const uint32_t* xs_hi, const uint32_t* xs_lo,
    uint32_t* so_hi, uint32_t* so_lo,
    const unsigned* xfl, unsigned* myfl,
    const float* __restrict__ bias)
{
    const int q = lane & 3, nl = lane >> 2;
    const int gr = tq >> 3, gu = tq & 7;
    const int unit = ug * 8 + gu;
    float bias4[4];
    #pragma unroll
    for (int g = 0; g < 4; g++) bias4[g] = bias[g * 256 + unit];

    // destination u64 index for this thread's (gr, unit); partner = unit^1
    const int ds = unit >> 4, dp = (unit >> 1) & 7, dhalf = unit & 1;
    const int dnl = gr & 7;
    const int dj = (dp >= 4 ? 2 : 0) + (gr >= 8 ? 1 : 0);
    const int du = ds * 128 + (dnl * 4 + (dp & 3)) * 4 + dj;
    const size_t hA0 = ((size_t)(L * 2 + 0) * 4 + bg) * 2048;
    const size_t hA1 = ((size_t)(L * 2 + 1) * 4 + bg) * 2048;

    float c_reg = 0.0f, h_reg = 0.0f;
    unsigned xseen = 0;
    const int barA = L * 2 + 1, barB = L * 2 + 2;
    const unsigned* xfl8 = xfl ? (xfl + sub * 8) : nullptr;

    for (int t = 0; t < tmax; t++) {
        float D[4][4];
        #pragma unroll
        for (int i = 0; i < 4; i++)
            #pragma unroll
            for (int j = 0; j < 4; j++) D[i][j] = 0.0f;

        // ---- x poll (flags) + x-part MMAs ----
        if (xfl8 && xseen < (unsigned)(t + 1)) {
            for (;;) {
                unsigned v = (lane < 8) ? ld_acq(xfl8 + lane) : 0xffffffffu;
                v = __reduce_min_sync(0xffffffffu, v);
                if (v >= (unsigned)(t + 1)) { xseen = v; break; }
            }
        }
        {
            const uint32_t* xh = xs_hi + (size_t)(t * 4 + bg) * (XD * 128)
                                 + (sub * XS4) * 128 + lane * 4;
            const uint32_t* xl = xs_lo + (size_t)(t * 4 + bg) * (XD * 128)
                                 + (sub * XS4) * 128 + lane * 4;
            #pragma unroll
            for (int s = 0; s < XS4; s++) {
                uint4 Ah = ld_cg_u4(xh + s * 128);
                uint4 Al = ld_cg_u4(xl + s * 128);
                #pragma unroll
                for (int i = 0; i < 4; i++) {
                    uint4 B = *reinterpret_cast<const uint4*>(
                        &w_frag[woff + (s * 4 + i) * 128 + lane * 4]);
                    mma16816(D[i], Ah.x, Ah.y, Ah.z, Ah.w, B.x, B.y);
                    mma16816(D[i], Al.x, Al.y, Al.z, Al.w, B.x, B.y);
                    mma16816(D[i], Ah.x, Ah.y, Ah.z, Ah.w, B.z, B.w);
                }
            }
        }

        // ---- h via tagged channel: spin on data, unpack, MMA ----
        if (t > 0) {
            const u64t* hb = g_hT + ((t & 1) ? hA1 : hA0);
            #pragma unroll
            for (int si = 0; si < 4; si++) {
                const u64t* hp = hb + (sub * 4 + si) * 128 + lane * 4;
                u64t v0, v1, v2, v3;
                for (;;) {
                    v0 = ld_rlx64(hp);     v1 = ld_rlx64(hp + 1);
                    v2 = ld_rlx64(hp + 2); v3 = ld_rlx64(hp + 3);
                    unsigned tg = (unsigned)t;
                    bool ok = ((unsigned)(v0 >> 48) == tg) &
                              ((unsigned)(v1 >> 48) == tg) &
                              ((unsigned)(v2 >> 48) == tg) &
                              ((unsigned)(v3 >> 48) == tg);
                    if (__all_sync(0xffffffffu, ok)) break;
                }
                uint32_t Ah0 = (uint32_t)v0, Ah1 = (uint32_t)v1;
                uint32_t Ah2 = (uint32_t)v2, Ah3 = (uint32_t)v3;
                uint32_t Al0 = __byte_perm((uint32_t)(v0 >> 32), 0, 0x1404);
                uint32_t Al1 = __byte_perm((uint32_t)(v1 >> 32), 0, 0x1404);
                uint32_t Al2 = __byte_perm((uint32_t)(v2 >> 32), 0, 0x1404);
                uint32_t Al3 = __byte_perm((uint32_t)(v3 >> 32), 0, 0x1404);
                #pragma unroll
                for (int i = 0; i < 4; i++) {
                    uint4 B = *reinterpret_cast<const uint4*>(
                        &w_frag[woff + ((XS4 + si) * 4 + i) * 128 + lane * 4]);
                    mma16816(D[i], Ah0, Ah1, Ah2, Ah3, B.x, B.y);
                    mma16816(D[i], Al0, Al1, Al2, Al3, B.x, B.y);
                    mma16816(D[i], Ah0, Ah1, Ah2, Ah3, B.z, B.w);
                }
            }
        }

        // ---- quad split-K partials (double-buffered) + single barrier ----
        float* pb = (t & 1) ? pb1 : pb0;
        #pragma unroll
        for (int i = 0; i < 4; i++) {
            *reinterpret_cast<float2*>(&pb[nl * 130 + sub * 32 + i * 8 + 2 * q]) =
                make_float2(D[i][0], D[i][1]);
            *reinterpret_cast<float2*>(&pb[(nl + 8) * 130 + sub * 32 + i * 8 + 2 * q]) =
                make_float2(D[i][2], D[i][3]);
        }
        asm volatile("bar.sync %0, 128;" :: "r"(barA) : "memory");

        // ---- gates ----
        float z[4];
        #pragma unroll
        for (int g = 0; g < 4; g++) {
            float a = bias4[g];
            #pragma unroll
            for (int w4 = 0; w4 < 4; w4++)
                a += pb[gr * 130 + w4 * 32 + g * 8 + gu];
            z[g] = a;
        }
        float si_ = sigx(z[0]), sf_ = sigx(z[1]), so_ = sigx(z[3]);
        float cn = sf_ * c_reg + si_ * tanhx(z[2]);
        float hn = so_ * tanhx(cn);
        bool m = (msk_sh[gr * 32 + (t >> 5)] >> (t & 31)) & 1u;
        if (!m) { cn = c_reg; hn = h_reg; }
        c_reg = cn; h_reg = hn;

        // ---- pack pair with partner lane, publish tagged u64 (h path) ----
        uint32_t vh = (uint32_t)__half_as_ushort(__float2half_rn(hn));
        float rres = hn - __half2float(__ushort_as_half((unsigned short)vh));
        uint32_t vl = (uint32_t)__half_as_ushort(__float2half_rn(rres));
        uint32_t hv = vh | (vl << 16);
        uint32_t pv = __shfl_xor_sync(0xffffffffu, hv, 1);
        if (dhalf == 0) {
            uint32_t hi_pair = (hv & 0xffffu) | (pv << 16);
            uint32_t lbA = ((hv >> 16) + 0x80u) >> 8 & 0xffu;
            uint32_t lbB = ((pv >> 16) + 0x80u) >> 8 & 0xffu;
            u64t val = (u64t)hi_pair | ((u64t)(lbA | (lbB << 8)) << 32)
                     | ((u64t)(unsigned)(t + 1) << 48);
            st_rlx64(g_hT + ((t & 1) ? hA0 : hA1) + du, val);   // parity (t+1)&1
            if (so_hi) {
                size_t su = (size_t)(t * 4 + bg) * 2048 + du;
                st_cg_u32(so_hi + su, hi_pair);
                st_cg_u32(so_lo + su, (hv >> 16) | (pv & 0xffff0000u));
            }
        }

        // ---- seq flag release (layers 0/1 only) ----
        if (myfl) {
            asm volatile("bar.sync %0, 128;" :: "r"(barB) : "memory");
            if (tq == 0) st_rel(myfl, (unsigned)(t + 1));
        }
    }
}

// ---------------------------------------------------------------------------
// 128 blocks (bg4 x ug32) x 384 threads = 3 layer-quads of 4 warps.
// ---------------------------------------------------------------------------
__global__ void __launch_bounds__(384, 1)
lstm_fused(const float* __restrict__ W0, const float* __restrict__ U0, const float* __restrict__ b0,
           const float* __restrict__ W1, const float* __restrict__ U1, const float* __restrict__ b1,
           const float* __restrict__ W2, const float* __restrict__ U2, const float* __restrict__ b2)
{
    extern __shared__ uint32_t smw[];
    uint32_t* w_frag = smw;                                       // 45056 u32
    float*    p_sh   = reinterpret_cast<float*>(smw + 45056);     // 6 x 2080
    uint32_t* msk_sh = reinterpret_cast<uint32_t*>(p_sh + 12480); // 512

    const int tid  = threadIdx.x;
    const int lane = tid & 31;
    const int warp = tid >> 5;
    const int L    = warp >> 2;
    const int sub  = warp & 3;
    const int tq   = tid & 127;
    const int bg   = blockIdx.x & 3;
    const int ug   = blockIdx.x >> 2;
    const int q    = lane & 3, nl = lane >> 2;

    for (int i = tid; i < 512; i += 384)
        msk_sh[i] = g_mbits[(bg * 16 + (i >> 5)) * 32 + (i & 31)];

    const float* W = (L == 0) ? W0 : (L == 1) ? W1 : W2;
    const float* U = (L == 0) ? U0 : (L == 1) ? U1 : U2;
    const float* bias = (L == 0) ? b0 : (L == 1) ? b1 : b2;
    const int KIN  = (L == 0) ? 128 : 256;
    const int XS4r = (L == 0) ? 2 : 4;
    const int woff = (L == 0) ? sub * 3072 : 12288 + (L - 1) * 16384 + sub * 4096;

    for (int slot = 0; slot < XS4r + 4; slot++) {
        int kg = (slot < XS4r) ? (sub * XS4r + slot) * 16
                               : KIN + (sub * 4 + slot - XS4r) * 16;
        #pragma unroll
        for (int i = 0; i < 4; i++) {
            int gcol = i * 256 + ug * 8 + nl;
            auto wu = [&](int k) -> float {
                return (k < KIN) ? W[(size_t)k * 1024 + gcol]
                                 : U[(size_t)(k - KIN) * 1024 + gcol];
            };
            int k0 = kg + 2 * q;
            uint32_t b0h, b0l, b1h, b1l;
            split2(wu(k0),     wu(k0 + 1), b0h, b0l);
            split2(wu(k0 + 8), wu(k0 + 9), b1h, b1l);
            *reinterpret_cast<uint4*>(&w_frag[woff + (slot * 4 + i) * 128 + lane * 4]) =
                make_uint4(b0h, b1h, b0l, b1l);
        }
    }
    __syncthreads();

    const int tmax = g_maxlen[bg];
    float* pb0 = p_sh + (L * 2 + 0) * 2080;
    float* pb1 = p_sh + (L * 2 + 1) * 2080;

    if (L == 0)
        run_layer<2, 8>(0, bg, ug, lane, sub, tq, tmax, w_frag, woff, pb0, pb1, msk_sh,
                        g_x0_hi, g_x0_lo, g_sA_hi, g_sA_lo,
                        nullptr, g_qflag + 0 * 128 + bg * 32 + ug, b0);
    else if (L == 1)
        run_layer<4, 16>(1, bg, ug, lane, sub, tq, tmax, w_frag, woff, pb0, pb1, msk_sh,
                         g_sA_hi, g_sA_lo, g_sB_hi, g_sB_lo,
                         g_qflag + 0 * 128 + bg * 32,
                         g_qflag + 1 * 128 + bg * 32 + ug, b1);
    else
        run_layer<4, 16>(2, bg, ug, lane, sub, tq, tmax, w_frag, woff, pb0, pb1, msk_sh,
                         g_sB_hi, g_sB_lo, nullptr, nullptr,
                         g_qflag + 1 * 128 + bg * 32, nullptr, b2);
}

// ---------------------------------------------------------------------------
__global__ void final_kernel(const float* __restrict__ dw,
                             const float* __restrict__ db,
                             float* __restrict__ out)
{
    int p = blockIdx.x, lane = threadIdx.x;
    int rA = 2 * p;
    int parity = g_maxlen[rA >> 4] & 1;            // last publish slot
    float s_acc = 0.0f;
    for (int pi = lane; pi < 128; pi += 32) {      // unit-pair index
        int unit = 2 * pi;
        int ds = unit >> 4, dp = pi & 7;
        float a0, a1, b0, b1;
        #pragma unroll
        for (int k = 0; k < 2; k++) {
            int r = rA + k;
            int bgr = r >> 4, rl = r & 15, nl2 = rl & 7;
            int dj = (dp >= 4 ? 2 : 0) + (rl >= 8 ? 1 : 0);
            size_t idx = ((size_t)(2 * 2 + parity) * 4 + bgr) * 2048
                       + ds * 128 + (nl2 * 4 + (dp & 3)) * 4 + dj;
            u64t v = g_hT[idx];
            float e0 = __half2float(__ushort_as_half((unsigned short)(v & 0xffffu)))
                     + __half2float(__ushort_as_half((unsigned short)(((v >> 32) & 0xffu) << 8)));
            float e1 = __half2float(__ushort_as_half((unsigned short)((v >> 16) & 0xffffu)))
                     + __half2float(__ushort_as_half((unsigned short)(((v >> 40) & 0xffu) << 8)));
            if (k == 0) { a0 = e0; a1 = e1; } else { b0 = e0; b1 = e1; }
        }
        float d0 = a0 - b0, d1 = a1 - b1;
        s_acc += d0 * d0 + d1 * d1;
    }
    #pragma unroll
    for (int off = 16; off; off >>= 1) s_acc += __shfl_xor_sync(0xffffffffu, s_acc, off);
    if (lane == 0) {
        float dist = sqrtf(s_acc);
        dist = fminf(fmaxf(dist, 1e-7f), 1e7f);
        out[p] = 1.0f / (1.0f + expf(-(dist * dw[0] + db[0])));
    }
}

// ---------------------------------------------------------------------------
extern "C" void kernel_launch(void* const* d_in, const int* in_sizes, int n_in,
                              void* d_out, int out_size)
{
    (void)in_sizes; (void)n_in; (void)out_size;
    const float* x  = (const float*)d_in[0];
    const float* W0 = (const float*)d_in[1];
    const float* U0 = (const float*)d_in[2];
    const float* b0 = (const float*)d_in[3];
    const float* W1 = (const float*)d_in[4];
    const float* U1 = (const float*)d_in[5];
    const float* b1 = (const float*)d_in[6];
    const float* W2 = (const float*)d_in[7];
    const float* U2 = (const float*)d_in[8];
    const float* b2 = (const float*)d_in[9];
    const float* dw = (const float*)d_in[10];
    const float* db = (const float*)d_in[11];
    float* out = (float*)d_out;

    const size_t smem = 45056u * 4 + 12480u * 4 + 512u * 4;   // 232192 B
    cudaFuncSetAttribute(lstm_fused, cudaFuncAttributeMaxDynamicSharedMemorySize,
                         (int)smem);

    init_kernel<<<8192, 256>>>(x);
    convert_x<<<4096, 256>>>(x);
    lstm_fused<<<128, 384, smem>>>(W0, U0, b0, W1, U1, b1, W2, U2, b2);
    final_kernel<<<32, 32>>>(dw, db, out);
}